// round 2
// baseline (speedup 1.0000x reference)
#include <cuda_runtime.h>
#include <cuda_bf16.h>

// Fused Swin window-attention (quadratic normalization), fp32 baseline.
// One CTA per window (B=4096). All intermediates live in SMEM:
//   x[49x384] -> per-head qkv[49x96] -> attn[49x49] -> head outs -> proj.
// Weights streamed global->SMEM in K=32 chunks (L2-resident across CTAs).

#define NW    49
#define DIMC  384
#define NH    12
#define HD    32
#define SCALE 0.17677669529663687f   // 32^-0.5

// SMEM layout (floats)
#define OFF_XW    0          // 18816: x during attention phases, w_proj chunks during proj
#define OFF_OUT   18816      // 18816: concatenated head outputs [49][384]
#define OFF_QKV   37632      // 49*97 (pad->4756): per-head q|k|v, row stride 97 (odd, conflict-free)
#define OFF_ATTN  42388      // 2401 (pad->2404)
#define OFF_RSUM  44792      // 49 (pad->56): reciprocal row sums
#define OFF_W     44848      // 32*96 = 3072: qkv weight chunk
#define OFF_BIAS  47920      // 169*12 = 2028: bias_table
#define OFF_REL   49948      // 2401 ints: rel_pos_index
#define SMEM_FLOATS 52349
#define SMEM_BYTES  (SMEM_FLOATS * 4)

#define QKV_STRIDE 97

__global__ void __launch_bounds__(256, 1)
win_attn_kernel(const float* __restrict__ x,
                const float* __restrict__ w_qkv,
                const float* __restrict__ w_proj,
                const float* __restrict__ b_proj,
                const float* __restrict__ bias_table,
                const int*   __restrict__ rel_idx,
                float*       __restrict__ out)
{
    extern __shared__ __align__(16) float smem[];
    float* sXW   = smem + OFF_XW;
    float* sOut  = smem + OFF_OUT;
    float* sQKV  = smem + OFF_QKV;
    float* sAttn = smem + OFF_ATTN;
    float* sRsum = smem + OFF_RSUM;
    float* sW    = smem + OFF_W;
    float* sBias = smem + OFF_BIAS;
    int*   sRel  = (int*)(smem + OFF_REL);

    const int tid  = threadIdx.x;
    const int warp = tid >> 5;
    const int lane = tid & 31;
    const int b    = blockIdx.x;

    // ---- Phase 0: stage x, bias table, rel index -------------------------
    {
        const float4* xg = (const float4*)(x + (size_t)b * NW * DIMC);
        #pragma unroll
        for (int i = 0; i < 19; ++i) {          // 4704 float4 / 256 = 18.375
            int idx = tid + i * 256;
            if (idx < NW * DIMC / 4) ((float4*)sXW)[idx] = xg[idx];
        }
        for (int i = tid; i < 169 * NH; i += 256) sBias[i] = bias_table[i];
        for (int i = tid; i < NW * NW; i += 256)  sRel[i]  = rel_idx[i];
    }
    __syncthreads();

    // rows handled by this thread: r = warp + 8*j  (warp0 -> 7 rows, else 6)
    // ---- Phase 1: per-head QKV + attention -------------------------------
    for (int h = 0; h < NH; ++h) {
        // --- QKV GEMM: [49x384] @ [384x96] -> sQKV (q scaled) ---
        float acc[7][3];
        #pragma unroll
        for (int j = 0; j < 7; ++j) { acc[j][0] = 0.f; acc[j][1] = 0.f; acc[j][2] = 0.f; }

        for (int kb = 0; kb < DIMC; kb += 32) {
            // load weight chunk [32][96]: cols = (q|k|v) of head h
            #pragma unroll
            for (int i = 0; i < 3; ++i) {
                int idx = tid + i * 256;            // < 768
                int kk  = idx / 24;
                int rem = idx % 24;
                int seg = rem >> 3;                 // 0=q 1=k 2=v
                int m   = rem & 7;
                float4 wv = *(const float4*)(w_qkv + (size_t)(kb + kk) * (3 * DIMC)
                                             + seg * DIMC + h * HD + m * 4);
                *(float4*)(sW + kk * 96 + seg * 32 + m * 4) = wv;
            }
            __syncthreads();
            #pragma unroll 8
            for (int kk = 0; kk < 32; ++kk) {
                float w0 = sW[kk * 96 + lane];
                float w1 = sW[kk * 96 + lane + 32];
                float w2 = sW[kk * 96 + lane + 64];
                #pragma unroll
                for (int j = 0; j < 7; ++j) {
                    // rows >=49 compute garbage but stay in-bounds; stores guarded
                    float xv = sXW[(warp + 8 * j) * DIMC + kb + kk];
                    acc[j][0] = fmaf(xv, w0, acc[j][0]);
                    acc[j][1] = fmaf(xv, w1, acc[j][1]);
                    acc[j][2] = fmaf(xv, w2, acc[j][2]);
                }
            }
            __syncthreads();
        }
        #pragma unroll
        for (int j = 0; j < 7; ++j) {
            int r = warp + 8 * j;
            if (r < NW) {
                sQKV[r * QKV_STRIDE + lane]      = acc[j][0] * SCALE;  // q pre-scaled
                sQKV[r * QKV_STRIDE + lane + 32] = acc[j][1];          // k
                sQKV[r * QKV_STRIDE + lane + 64] = acc[j][2];          // v
            }
        }
        __syncthreads();

        // --- scores: attn[r][c] = (q.k + bias)^2 ---
        for (int idx = tid; idx < NW * NW; idx += 256) {
            int r = idx / NW, c = idx - r * NW;
            const float* qr = sQKV + r * QKV_STRIDE;
            const float* kc = sQKV + c * QKV_STRIDE + 32;
            float s = 0.f;
            #pragma unroll
            for (int d = 0; d < HD; ++d) s = fmaf(qr[d], kc[d], s);
            s += sBias[sRel[idx] * NH + h];
            sAttn[idx] = s * s;
        }
        __syncthreads();

        // --- row sums -> reciprocal ---
        for (int r = warp; r < NW; r += 8) {
            float s = sAttn[r * NW + lane];
            if (lane + 32 < NW) s += sAttn[r * NW + lane + 32];
            #pragma unroll
            for (int o = 16; o > 0; o >>= 1) s += __shfl_xor_sync(0xFFFFFFFFu, s, o);
            if (lane == 0) sRsum[r] = 1.0f / (s + 1e-6f);
        }
        __syncthreads();

        // --- out_h = (attn/rowsum) @ v, write into sOut columns h*32.. ---
        for (int idx = tid; idx < NW * HD; idx += 256) {
            int r = idx >> 5, d = idx & 31;
            const float* ar = sAttn + r * NW;
            float a = 0.f;
            #pragma unroll
            for (int c = 0; c < NW; ++c) a = fmaf(ar[c], sQKV[c * QKV_STRIDE + 64 + d], a);
            sOut[r * DIMC + h * HD + d] = a * sRsum[r];
        }
        __syncthreads();
    }

    // ---- Phase 2: projection  out = sOut @ w_proj + b_proj ---------------
    float bpr[12];
    #pragma unroll
    for (int m = 0; m < 12; ++m) bpr[m] = b_proj[lane + 32 * m];

    float pacc[7][12];
    #pragma unroll
    for (int j = 0; j < 7; ++j)
        #pragma unroll
        for (int m = 0; m < 12; ++m) pacc[j][m] = 0.f;

    for (int kb = 0; kb < DIMC; kb += 32) {
        // load w_proj chunk [32][384] into sXW (x no longer needed)
        #pragma unroll
        for (int i = 0; i < 12; ++i) {
            int idx = tid + i * 256;              // < 3072
            int kk  = idx / 96;
            int m   = idx - kk * 96;
            *(float4*)(sXW + kk * DIMC + m * 4) =
                *(const float4*)(w_proj + (size_t)(kb + kk) * DIMC + m * 4);
        }
        __syncthreads();
        #pragma unroll 4
        for (int kk = 0; kk < 32; ++kk) {
            float wv[12];
            #pragma unroll
            for (int m = 0; m < 12; ++m) wv[m] = sXW[kk * DIMC + lane + 32 * m];
            #pragma unroll
            for (int j = 0; j < 7; ++j) {
                float xv = sOut[(warp + 8 * j) * DIMC + kb + kk];  // in-bounds garbage for r>=49
                #pragma unroll
                for (int m = 0; m < 12; ++m) pacc[j][m] = fmaf(xv, wv[m], pacc[j][m]);
            }
        }
        __syncthreads();
    }

    float* og = out + (size_t)b * NW * DIMC;
    #pragma unroll
    for (int j = 0; j < 7; ++j) {
        int r = warp + 8 * j;
        if (r < NW) {
            #pragma unroll
            for (int m = 0; m < 12; ++m)
                og[r * DIMC + lane + 32 * m] = pacc[j][m] + bpr[m];
        }
    }
}

extern "C" void kernel_launch(void* const* d_in, const int* in_sizes, int n_in,
                              void* d_out, int out_size) {
    const float* x          = (const float*)d_in[0];
    const float* w_qkv      = (const float*)d_in[1];
    const float* w_proj     = (const float*)d_in[2];
    const float* b_proj     = (const float*)d_in[3];
    const float* bias_table = (const float*)d_in[4];
    const int*   rel_idx    = (const int*)d_in[5];
    float* out = (float*)d_out;

    int B = in_sizes[0] / (NW * DIMC);   // 4096

    cudaFuncSetAttribute(win_attn_kernel,
                         cudaFuncAttributeMaxDynamicSharedMemorySize, SMEM_BYTES);
    win_attn_kernel<<<B, 256, SMEM_BYTES>>>(x, w_qkv, w_proj, b_proj,
                                            bias_table, rel_idx, out);
}

// round 4
// speedup vs baseline: 2.2073x; 2.2073x over previous
#include <cuda_runtime.h>
#include <cuda_bf16.h>
#include <cstdint>

// ============================================================================
// Swin window attention (quadratic norm), split-bf16 HMMA pipeline (no tcgen05;
// harness builds for plain sm_103 target, so only non-'a' ISA is available):
//   1) split x / w (transposed) into bf16 hi/lo
//   2) QKV GEMM  [200704x384]@[384x1152] -> fp32 scratch   (mma.sync, 3-term)
//   3) per-window attention (fp32 FFMA) -> split-bf16 scratch
//   4) proj GEMM [200704x384]@[384x384] + bias -> out      (mma.sync, 3-term)
// ============================================================================

#define NW     49
#define DIMC   384
#define NH     12
#define HD     32
#define SCALEF 0.17677669529663687f
#define MTOT   200704            // 4096 * 49 = 1568 * 128
#define NQKV   1152

// ---- scratch (device globals; no runtime allocation) -----------------------
__device__ __nv_bfloat16 g_xh[(size_t)MTOT * DIMC];
__device__ __nv_bfloat16 g_xl[(size_t)MTOT * DIMC];
__device__ __nv_bfloat16 g_wqkvT_h[NQKV * DIMC];
__device__ __nv_bfloat16 g_wqkvT_l[NQKV * DIMC];
__device__ __nv_bfloat16 g_wprojT_h[DIMC * DIMC];
__device__ __nv_bfloat16 g_wprojT_l[DIMC * DIMC];
__device__ float         g_qkv[(size_t)MTOT * NQKV];
__device__ __nv_bfloat16 g_ah[(size_t)MTOT * DIMC];
__device__ __nv_bfloat16 g_al[(size_t)MTOT * DIMC];

// ---- helpers ----------------------------------------------------------------
__device__ __forceinline__ uint32_t smem_to_u32(const void* p) {
    uint32_t a;
    asm("{ .reg .u64 t; cvta.to.shared.u64 t, %1; cvt.u32.u64 %0, t; }"
        : "=r"(a) : "l"(p));
    return a;
}

__device__ __forceinline__ void ldsm_x4(uint32_t& r0, uint32_t& r1,
                                        uint32_t& r2, uint32_t& r3, uint32_t a) {
    asm volatile("ldmatrix.sync.aligned.m8n8.x4.shared.b16 {%0,%1,%2,%3}, [%4];"
                 : "=r"(r0), "=r"(r1), "=r"(r2), "=r"(r3) : "r"(a));
}
__device__ __forceinline__ void ldsm_x2(uint32_t& r0, uint32_t& r1, uint32_t a) {
    asm volatile("ldmatrix.sync.aligned.m8n8.x2.shared.b16 {%0,%1}, [%2];"
                 : "=r"(r0), "=r"(r1) : "r"(a));
}
__device__ __forceinline__ void mma_bf16(float* d, const uint32_t* a, const uint32_t* b) {
    asm volatile("mma.sync.aligned.m16n8k16.row.col.f32.bf16.bf16.f32 "
                 "{%0,%1,%2,%3}, {%4,%5,%6,%7}, {%8,%9}, {%0,%1,%2,%3};"
                 : "+f"(d[0]), "+f"(d[1]), "+f"(d[2]), "+f"(d[3])
                 : "r"(a[0]), "r"(a[1]), "r"(a[2]), "r"(a[3]), "r"(b[0]), "r"(b[1]));
}
__device__ __forceinline__ void cp16(uint32_t dst, const void* src) {
    asm volatile("cp.async.cg.shared.global [%0], [%1], 16;" :: "r"(dst), "l"(src));
}
#define CP_COMMIT() asm volatile("cp.async.commit_group;" ::: "memory")
#define CP_WAIT(n)  asm volatile("cp.async.wait_group %0;" :: "n"(n) : "memory")

__device__ __forceinline__ void split2(float v, __nv_bfloat16& h, __nv_bfloat16& l) {
    h = __float2bfloat16(v);
    l = __float2bfloat16(v - __bfloat162float(h));
}

// ============================================================================
// Kernel 1: split x (fp32 -> bf16 hi/lo), vectorized
// ============================================================================
__global__ void split_x_kernel(const float* __restrict__ x,
                               __nv_bfloat16* __restrict__ xh,
                               __nv_bfloat16* __restrict__ xl, int n4) {
    int i = blockIdx.x * 256 + threadIdx.x;
    if (i >= n4) return;
    float4 v = ((const float4*)x)[i];
    __nv_bfloat16 h0, h1, h2, h3, l0, l1, l2, l3;
    split2(v.x, h0, l0); split2(v.y, h1, l1);
    split2(v.z, h2, l2); split2(v.w, h3, l3);
    ushort4 hv = { __bfloat16_as_ushort(h0), __bfloat16_as_ushort(h1),
                   __bfloat16_as_ushort(h2), __bfloat16_as_ushort(h3) };
    ushort4 lv = { __bfloat16_as_ushort(l0), __bfloat16_as_ushort(l1),
                   __bfloat16_as_ushort(l2), __bfloat16_as_ushort(l3) };
    ((ushort4*)xh)[i] = hv;
    ((ushort4*)xl)[i] = lv;
}

// ============================================================================
// Kernel 2: split + transpose weight: dst[n][k] = split(src[k*srcld + n])
// ============================================================================
__global__ void splitT_kernel(const float* __restrict__ src,
                              __nv_bfloat16* __restrict__ dh,
                              __nv_bfloat16* __restrict__ dl,
                              int Nrows, int Kcols, int srcld) {
    int i = blockIdx.x * 256 + threadIdx.x;
    if (i >= Nrows * Kcols) return;
    int n = i / Kcols, k = i - n * Kcols;
    __nv_bfloat16 h, l;
    split2(src[(size_t)k * srcld + n], h, l);
    dh[i] = h; dl[i] = l;
}

// ============================================================================
// Kernel 3: split-bf16 HMMA GEMM. CTA tile 128x128, K-chunk 64, 2-stage cp.async.
//   C[m][n] = sum_k (Ah+Al)[m][k]*(Bh+Bl)[n][k]   (3 of 4 cross terms)
//   A: [M][384] bf16 row-major;  B: [N][384] bf16 row-major (k-contiguous)
// smem per stage: Ah|Al|Bh|Bl tiles, 128 rows x 144B (64 bf16 + 16B pad)
// ============================================================================
#define TILE_B   18432                 // 128 * 144
#define STAGE_B  (4 * TILE_B)          // 73728
#define GEMM_SMEM (2 * STAGE_B)        // 147456

__global__ void __launch_bounds__(256, 1)
gemm3_kernel(const __nv_bfloat16* __restrict__ Ah,
             const __nv_bfloat16* __restrict__ Al,
             const __nv_bfloat16* __restrict__ Bh,
             const __nv_bfloat16* __restrict__ Bl,
             float* __restrict__ C, int ldc,
             const float* __restrict__ bias) {
    extern __shared__ __align__(16) char smem[];
    const int tid  = threadIdx.x;
    const int warp = tid >> 5;
    const int lane = tid & 31;
    const uint32_t sb = smem_to_u32(smem);
    const int m0 = blockIdx.y * 128;
    const int n0 = blockIdx.x * 128;
    const int m_warp = (warp >> 2) * 64;   // 0 / 64
    const int n_warp = (warp & 3) * 32;    // 0..96

    float acc[4][4][4];
    #pragma unroll
    for (int mt = 0; mt < 4; ++mt)
        #pragma unroll
        for (int nt = 0; nt < 4; ++nt)
            #pragma unroll
            for (int e = 0; e < 4; ++e) acc[mt][nt][e] = 0.f;

    // ---- stage loader (cp.async): 4 tiles x 1024 x 16B chunks ----
    auto load_stage = [&](int stage, int ks) {
        const int k0 = ks * 64;
        const __nv_bfloat16* srcs[4] = { Ah, Al, Bh, Bl };
        const int r0s[4] = { m0, m0, n0, n0 };
        #pragma unroll
        for (int t = 0; t < 4; ++t) {
            const char* src = (const char*)(srcs[t] + (size_t)r0s[t] * DIMC + k0);
            uint32_t dst = sb + stage * STAGE_B + t * TILE_B;
            #pragma unroll
            for (int i = 0; i < 4; ++i) {
                int u = tid + i * 256;        // 0..1023
                int row = u >> 3, ch = u & 7;
                cp16(dst + row * 144 + ch * 16,
                     src + (size_t)row * (DIMC * 2) + ch * 16);
            }
        }
    };

    load_stage(0, 0);
    CP_COMMIT();

    const int NKS = DIMC / 64;   // 6
    for (int ks = 0; ks < NKS; ++ks) {
        const int s = ks & 1;
        __syncthreads();                          // stage 1-s free for reuse
        if (ks + 1 < NKS) {
            load_stage(1 - s, ks + 1);
            CP_COMMIT();
            CP_WAIT(1);                           // stage s resident
        } else {
            CP_WAIT(0);
        }
        __syncthreads();

        const uint32_t aBase  = sb + s * STAGE_B;
        const uint32_t alBase = aBase + TILE_B;
        const uint32_t bhBase = aBase + 2 * TILE_B;
        const uint32_t blBase = aBase + 3 * TILE_B;
        const int rB = lane & 7, jB = (lane >> 3) & 1;
        const int rA = lane & 7, jA8 = ((lane >> 3) & 1) * 8, kA16 = ((lane >> 4) & 1) * 16;

        #pragma unroll
        for (int kk = 0; kk < 4; ++kk) {
            uint32_t bh[4][2], bl[4][2];
            #pragma unroll
            for (int nt = 0; nt < 4; ++nt) {
                uint32_t off = (uint32_t)(n_warp + nt * 8 + rB) * 144 + kk * 32 + jB * 16;
                ldsm_x2(bh[nt][0], bh[nt][1], bhBase + off);
                ldsm_x2(bl[nt][0], bl[nt][1], blBase + off);
            }
            #pragma unroll
            for (int mt = 0; mt < 4; ++mt) {
                uint32_t off = (uint32_t)(m_warp + mt * 16 + jA8 + rA) * 144 + kk * 32 + kA16;
                uint32_t ah[4], al[4];
                ldsm_x4(ah[0], ah[1], ah[2], ah[3], aBase  + off);
                ldsm_x4(al[0], al[1], al[2], al[3], alBase + off);
                #pragma unroll
                for (int nt = 0; nt < 4; ++nt) {
                    mma_bf16(acc[mt][nt], ah, bh[nt]);
                    mma_bf16(acc[mt][nt], ah, bl[nt]);
                    mma_bf16(acc[mt][nt], al, bh[nt]);
                }
            }
        }
    }

    // ---- epilogue: direct float2 stores (lane quad covers a 32B sector) ----
    const int mrow  = m0 + m_warp + (lane >> 2);
    const int ncol0 = n0 + n_warp + (lane & 3) * 2;
    #pragma unroll
    for (int mt = 0; mt < 4; ++mt) {
        #pragma unroll
        for (int nt = 0; nt < 4; ++nt) {
            int m = mrow + mt * 16;
            int n = ncol0 + nt * 8;
            float2 v0 = { acc[mt][nt][0], acc[mt][nt][1] };
            float2 v1 = { acc[mt][nt][2], acc[mt][nt][3] };
            if (bias) {
                float2 bv = *(const float2*)&bias[n];
                v0.x += bv.x; v0.y += bv.y; v1.x += bv.x; v1.y += bv.y;
            }
            *(float2*)&C[(size_t)m * ldc + n]       = v0;
            *(float2*)&C[(size_t)(m + 8) * ldc + n] = v1;
        }
    }
}

// ============================================================================
// Kernel 4: per-window attention (fp32), reads g_qkv, writes split bf16 out.
// ============================================================================
__global__ void __launch_bounds__(256)
attn_kernel(const float* __restrict__ qkv,
            const float* __restrict__ bias_table,
            const int*   __restrict__ rel_idx,
            __nv_bfloat16* __restrict__ oh,
            __nv_bfloat16* __restrict__ ol) {
    __shared__ __align__(16) float sQ[NW * 36];
    __shared__ float sK[NW * 33];
    __shared__ float sV[NW * 33];
    __shared__ __align__(16) float sAttn[NW * 52];
    __shared__ float sBias[169 * NH];
    __shared__ int   sRel[NW * NW];

    const int tid = threadIdx.x, warp = tid >> 5, lane = tid & 31;
    const size_t base = (size_t)blockIdx.x * NW;

    for (int i = tid; i < 169 * NH; i += 256) sBias[i] = bias_table[i];
    for (int i = tid; i < NW * NW; i += 256)  sRel[i]  = rel_idx[i];
    for (int i = tid; i < NW; i += 256) {      // zero pad cols 49..51
        sAttn[i * 52 + 49] = 0.f; sAttn[i * 52 + 50] = 0.f; sAttn[i * 52 + 51] = 0.f;
    }
    __syncthreads();

    for (int h = 0; h < NH; ++h) {
        for (int i = tid; i < NW * 96; i += 256) {
            int r = i / 96, c = i - r * 96;
            int seg = c >> 5, d = c & 31;
            float v = qkv[(base + r) * NQKV + seg * DIMC + h * HD + d];
            if (seg == 0)      sQ[r * 36 + d] = v * SCALEF;
            else if (seg == 1) sK[r * 33 + d] = v;
            else               sV[r * 33 + d] = v;
        }
        __syncthreads();

        // scores: attn[r][c] = (q.k + bias)^2 ; K columns held in registers
        {
            const int c0 = lane;
            const int c1 = (lane + 32 < NW) ? lane + 32 : NW - 1;
            float k0r[HD], k1r[HD];
            #pragma unroll
            for (int d = 0; d < HD; ++d) { k0r[d] = sK[c0 * 33 + d]; k1r[d] = sK[c1 * 33 + d]; }
            for (int r = warp; r < NW; r += 8) {
                float s0 = 0.f, s1 = 0.f;
                #pragma unroll
                for (int j = 0; j < 8; ++j) {
                    float4 q4 = *(const float4*)&sQ[r * 36 + j * 4];
                    s0 = fmaf(q4.x, k0r[j*4+0], s0); s1 = fmaf(q4.x, k1r[j*4+0], s1);
                    s0 = fmaf(q4.y, k0r[j*4+1], s0); s1 = fmaf(q4.y, k1r[j*4+1], s1);
                    s0 = fmaf(q4.z, k0r[j*4+2], s0); s1 = fmaf(q4.z, k1r[j*4+2], s1);
                    s0 = fmaf(q4.w, k0r[j*4+3], s0); s1 = fmaf(q4.w, k1r[j*4+3], s1);
                }
                float b0 = sBias[sRel[r * NW + c0] * NH + h];
                float t0 = s0 + b0;
                sAttn[r * 52 + c0] = t0 * t0;
                if (lane + 32 < NW) {
                    float b1 = sBias[sRel[r * NW + lane + 32] * NH + h];
                    float t1 = s1 + b1;
                    sAttn[r * 52 + lane + 32] = t1 * t1;
                }
            }
        }
        __syncthreads();

        // per-warp rowsums, all lanes get the value (butterfly)
        float rs[7];
        #pragma unroll
        for (int j = 0; j < 7; ++j) {
            int r = warp + 8 * j;
            if (r < NW) {
                float s = sAttn[r * 52 + lane];
                if (lane + 32 < NW) s += sAttn[r * 52 + lane + 32];
                #pragma unroll
                for (int o = 16; o > 0; o >>= 1) s += __shfl_xor_sync(0xFFFFFFFFu, s, o);
                rs[j] = 1.0f / (s + 1e-6f);
            } else rs[j] = 0.f;
        }

        // out_h[r][d] = sum_c attn[r][c] * v[c][d]; lane -> d
        {
            float accv[7];
            #pragma unroll
            for (int j = 0; j < 7; ++j) accv[j] = 0.f;
            for (int cb = 0; cb < NW; cb += 4) {
                float v0 = sV[cb * 33 + lane];
                float v1 = (cb + 1 < NW) ? sV[(cb + 1) * 33 + lane] : 0.f;
                float v2 = (cb + 2 < NW) ? sV[(cb + 2) * 33 + lane] : 0.f;
                float v3 = (cb + 3 < NW) ? sV[(cb + 3) * 33 + lane] : 0.f;
                #pragma unroll
                for (int j = 0; j < 7; ++j) {
                    int r = warp + 8 * j;
                    if (r < NW) {
                        float4 a4 = *(const float4*)&sAttn[r * 52 + cb];
                        accv[j] = fmaf(a4.x, v0, accv[j]);
                        accv[j] = fmaf(a4.y, v1, accv[j]);
                        accv[j] = fmaf(a4.z, v2, accv[j]);
                        accv[j] = fmaf(a4.w, v3, accv[j]);
                    }
                }
            }
            #pragma unroll
            for (int j = 0; j < 7; ++j) {
                int r = warp + 8 * j;
                if (r < NW) {
                    float o = accv[j] * rs[j];
                    __nv_bfloat16 hv, lv;
                    split2(o, hv, lv);
                    size_t oi = (base + r) * DIMC + h * HD + lane;
                    oh[oi] = hv; ol[oi] = lv;
                }
            }
        }
        __syncthreads();
    }
}

// ============================================================================
// launch
// ============================================================================
extern "C" void kernel_launch(void* const* d_in, const int* in_sizes, int n_in,
                              void* d_out, int out_size) {
    const float* x          = (const float*)d_in[0];
    const float* w_qkv      = (const float*)d_in[1];
    const float* w_proj     = (const float*)d_in[2];
    const float* b_proj     = (const float*)d_in[3];
    const float* bias_table = (const float*)d_in[4];
    const int*   rel_idx    = (const int*)d_in[5];
    float* out = (float*)d_out;

    void *p_xh, *p_xl, *p_wqh, *p_wql, *p_wph, *p_wpl, *p_qkv, *p_ah, *p_al;
    cudaGetSymbolAddress(&p_xh,  g_xh);
    cudaGetSymbolAddress(&p_xl,  g_xl);
    cudaGetSymbolAddress(&p_wqh, g_wqkvT_h);
    cudaGetSymbolAddress(&p_wql, g_wqkvT_l);
    cudaGetSymbolAddress(&p_wph, g_wprojT_h);
    cudaGetSymbolAddress(&p_wpl, g_wprojT_l);
    cudaGetSymbolAddress(&p_qkv, g_qkv);
    cudaGetSymbolAddress(&p_ah,  g_ah);
    cudaGetSymbolAddress(&p_al,  g_al);

    cudaFuncSetAttribute(gemm3_kernel,
                         cudaFuncAttributeMaxDynamicSharedMemorySize, GEMM_SMEM);

    // 1) splits
    int n4 = (MTOT * DIMC) / 4;
    split_x_kernel<<<n4 / 256, 256>>>(x, (__nv_bfloat16*)p_xh, (__nv_bfloat16*)p_xl, n4);
    splitT_kernel<<<(NQKV * DIMC + 255) / 256, 256>>>(w_qkv,
        (__nv_bfloat16*)p_wqh, (__nv_bfloat16*)p_wql, NQKV, DIMC, NQKV);
    splitT_kernel<<<(DIMC * DIMC + 255) / 256, 256>>>(w_proj,
        (__nv_bfloat16*)p_wph, (__nv_bfloat16*)p_wpl, DIMC, DIMC, DIMC);

    // 2) QKV GEMM -> g_qkv
    gemm3_kernel<<<dim3(NQKV / 128, MTOT / 128), 256, GEMM_SMEM>>>(
        (const __nv_bfloat16*)p_xh, (const __nv_bfloat16*)p_xl,
        (const __nv_bfloat16*)p_wqh, (const __nv_bfloat16*)p_wql,
        (float*)p_qkv, NQKV, nullptr);

    // 3) attention -> split bf16 scratch
    attn_kernel<<<MTOT / NW, 256>>>((const float*)p_qkv, bias_table, rel_idx,
                                    (__nv_bfloat16*)p_ah, (__nv_bfloat16*)p_al);

    // 4) proj GEMM + bias -> out
    gemm3_kernel<<<dim3(DIMC / 128, MTOT / 128), 256, GEMM_SMEM>>>(
        (const __nv_bfloat16*)p_ah, (const __nv_bfloat16*)p_al,
        (const __nv_bfloat16*)p_wph, (const __nv_bfloat16*)p_wpl,
        out, DIMC, b_proj);
}